// round 16
// baseline (speedup 1.0000x reference)
#include <cuda_runtime.h>

// LSTM: T=512, B=4096, IN=1, H=12.
// R16 = R9 parallelism (2048 warps; one batch per 16-lane segment) combined
// with R14/R15 mechanics:
//   - MUFU.TANH activations, sigmoid rows pre-scaled by 0.5
//   - packed f32x2 matvec (fma.rn.f32x2)
//   - h broadcast via double-buffered SMEM (1 STS + syncwarp + 6 LDS.64)
//   - fc output as redundant packed register dot (no butterfly shuffles)
// ~63 instr/warp/step at 3.46 warps/SMSP.

#define T_STEPS 512
#define BATCH   4096
#define HID     12

typedef unsigned long long ull;

__device__ __forceinline__ ull pack2(float lo, float hi) {
    ull r;
    asm("mov.b64 %0, {%1, %2};" : "=l"(r) : "f"(lo), "f"(hi));
    return r;
}
__device__ __forceinline__ void unpack2(ull v, float& lo, float& hi) {
    asm("mov.b64 {%0, %1}, %2;" : "=f"(lo), "=f"(hi) : "l"(v));
}
__device__ __forceinline__ ull fma2(ull a, ull b, ull c) {
    ull d;
    asm("fma.rn.f32x2 %0, %1, %2, %3;" : "=l"(d) : "l"(a), "l"(b), "l"(c));
    return d;
}
__device__ __forceinline__ float tanh_mufu(float x) {
    float r; asm("tanh.approx.f32 %0, %1;" : "=f"(r) : "f"(x)); return r;
}

__global__ void __launch_bounds__(128, 4)
lstm_kernel(const float* __restrict__ X,
            const float* __restrict__ W_ih,
            const float* __restrict__ W_hh,
            const float* __restrict__ b_ih,
            const float* __restrict__ b_hh,
            const float* __restrict__ fc_w,
            const float* __restrict__ fc_b,
            float* __restrict__ Y)
{
    // [buf][segment][16 floats]; 8 segments per CTA (128 threads).
    __shared__ float hsh[2][8][16];

    const int tid = threadIdx.x;
    const int seg = tid >> 4;                       // segment in CTA (0..7)
    const int ls  = tid & 15;                       // lane within segment
    const int b   = blockIdx.x * 8 + seg;           // batch element (512*8=4096)
    const int u   = (ls < 12) ? ls : 11;            // hidden unit (idle clamp)

    // ---- Register-resident weights ----
    // Gate order i,f,g,o; sigmoid rows (i,f,o) pre-scaled by 0.5 so
    // sigma(v) = 0.5*tanh(v') + 0.5 is 1 MUFU + 1 FMA.
    ull   w2[4][6];
    float wih[4], bias[4];
#pragma unroll
    for (int g = 0; g < 4; ++g) {
        const int   row = g * HID + u;
        const float s   = (g == 2) ? 1.0f : 0.5f;
#pragma unroll
        for (int k = 0; k < 6; ++k)
            w2[g][k] = pack2(s * W_hh[row * HID + 2 * k],
                             s * W_hh[row * HID + 2 * k + 1]);
        wih[g]  = s * W_ih[row];
        bias[g] = s * (b_ih[row] + b_hh[row]);
    }
    ull fc2[6];
#pragma unroll
    for (int k = 0; k < 6; ++k)
        fc2[k] = pack2(fc_w[2 * k], fc_w[2 * k + 1]);
    const float fcb = fc_b[0];

    float* const hb0 = &hsh[0][seg][0];
    float* const hb1 = &hsh[1][seg][0];

    // ---- State ----
    ull h2[6];
#pragma unroll
    for (int k = 0; k < 6; ++k) h2[k] = 0ULL;       // h0 = 0
    float c = 0.0f;

    const float* xp = X + b;
    float*       yp = Y + b;
    float x = xp[0];

#pragma unroll 2
    for (int t = 0; t < T_STEPS; ++t) {
        // Prefetch next input (independent of recurrence).
        float xn = 0.0f;
        if (t + 1 < T_STEPS) xn = xp[BATCH];

        // ---- gates = x*W_ih + bias + h @ W_hh^T (packed f32x2 dots) ----
        float gate[4];
#pragma unroll
        for (int g = 0; g < 4; ++g) {
            ull acc = pack2(fmaf(x, wih[g], bias[g]), 0.0f);
#pragma unroll
            for (int k = 0; k < 6; ++k)
                acc = fma2(h2[k], w2[g][k], acc);
            float lo, hi; unpack2(acc, lo, hi);
            gate[g] = lo + hi;
        }

        // ---- activations: one MUFU.TANH each ----
        const float gg = tanh_mufu(gate[2]);
        const float ig = fmaf(0.5f, tanh_mufu(gate[0]), 0.5f);
        const float fg = fmaf(0.5f, tanh_mufu(gate[1]), 0.5f);
        const float og = fmaf(0.5f, tanh_mufu(gate[3]), 0.5f);

        c = fmaf(fg, c, ig * gg);
        const float h = og * tanh_mufu(c);

        // ---- publish h (double-buffered smem broadcast) ----
        float* const hb = (t & 1) ? hb1 : hb0;
        if (ls < 12) hb[ls] = h;
        __syncwarp();

        // ---- gather h as aligned f32x2 pairs (LDS.64 broadcast) ----
#pragma unroll
        for (int k = 0; k < 6; ++k)
            h2[k] = *(const ull*)(hb + 2 * k);

        // ---- fc output: redundant packed dot (no shuffles) ----
        ull ya = pack2(fcb, 0.0f);
#pragma unroll
        for (int k = 0; k < 6; ++k)
            ya = fma2(h2[k], fc2[k], ya);
        float yl, yh; unpack2(ya, yl, yh);
        if (ls == 0) *yp = yl + yh;

        yp += BATCH;
        xp += BATCH;
        x = xn;
    }
}

extern "C" void kernel_launch(void* const* d_in, const int* in_sizes, int n_in,
                              void* d_out, int out_size)
{
    const float* X    = (const float*)d_in[0];
    const float* W_ih = (const float*)d_in[1];
    const float* W_hh = (const float*)d_in[2];
    const float* b_ih = (const float*)d_in[3];
    const float* b_hh = (const float*)d_in[4];
    const float* fc_w = (const float*)d_in[5];
    const float* fc_b = (const float*)d_in[6];
    float* Y = (float*)d_out;

    // 4096 batches * 16 lanes = 65536 threads; 128 threads/block -> 512 blocks.
    lstm_kernel<<<512, 128>>>(X, W_ih, W_hh, b_ih, b_hh, fc_w, fc_b, Y);
}